// round 4
// baseline (speedup 1.0000x reference)
#include <cuda_runtime.h>
#include <stdint.h>
#include <math.h>

#define NB 2048
#define ND 256
#define NDT 768
#define HS 512   // hash slots per subset

// accumulators: [0]=mse sumsq, [1..7]=entropy row-sums S1,S2,S3,S13,S23,S12,S123
__device__ double g_acc[8];
__device__ double g_ck[14];          // ce,kl sums per 7 masks
__device__ unsigned int g_minbits[3];
__device__ unsigned int g_done;

__device__ __forceinline__ unsigned int fkey(float f) {
    unsigned int u = __float_as_uint(f);
    return (u & 0x80000000u) ? ~u : (u | 0x80000000u);
}
__device__ __forceinline__ float funkey(unsigned int u) {
    return __uint_as_float((u & 0x80000000u) ? (u & 0x7FFFFFFFu) : ~u);
}

__global__ void init_kernel() {
    int t = threadIdx.x;
    if (t < 8) g_acc[t] = 0.0;
    if (t < 14) g_ck[t] = 0.0;
    if (t < 3) g_minbits[t] = 0xFFFFFFFFu;
    if (t == 0) g_done = 0u;
}

// ------- stats: per-row softmax stats + fused MSE + fused ce/kl (hsoft) -------
__global__ void stats_kernel(const float* __restrict__ d1, const float* __restrict__ d2,
                             const float* __restrict__ d3,
                             const float* __restrict__ o1, const float* __restrict__ o2,
                             const float* __restrict__ o3,
                             const float* __restrict__ data, const float* __restrict__ outp) {
    __shared__ double sacc[14];
    int tid = blockIdx.x * blockDim.x + threadIdx.x;
    int lane = threadIdx.x & 31;
    if (threadIdx.x < 14) sacc[threadIdx.x] = 0.0;

    // --- fused MSE over [NB, NDT] via float4 grid-stride ---
    {
        const float4* a = (const float4*)data;
        const float4* b = (const float4*)outp;
        int n4 = NB * NDT / 4;
        int stride = gridDim.x * blockDim.x;
        float s = 0.f;
        for (int i = tid; i < n4; i += stride) {
            float4 x = a[i], y = b[i];
            float e0 = x.x - y.x, e1 = x.y - y.y, e2 = x.z - y.z, e3 = x.w - y.w;
            s += e0 * e0 + e1 * e1 + e2 * e2 + e3 * e3;
        }
        for (int o = 16; o; o >>= 1) s += __shfl_xor_sync(0xffffffffu, s, o);
        if (lane == 0) atomicAdd(&g_acc[0], (double)s);
    }

    // --- per-row stats: one warp per row (grid = exactly NB warps) ---
    int gw = tid >> 5;
    const float* ds[3] = {d1, d2, d3};
    const float* os[3] = {o1, o2, o3};
    float amD[3], asD[3], atO[3], auD[3], amO[3], asO[3];
#pragma unroll
    for (int k = 0; k < 3; k++) {
        const float* dp = ds[k] + gw * ND;
        const float* op = os[k] + gw * ND;
        float vd[8], vo[8];
#pragma unroll
        for (int i = 0; i < 8; i++) { vd[i] = dp[lane + 32 * i]; vo[i] = op[lane + 32 * i]; }
        float mD = -INFINITY, mO = -INFINITY, mn = INFINITY;
#pragma unroll
        for (int i = 0; i < 8; i++) {
            mD = fmaxf(mD, vd[i]); mO = fmaxf(mO, vo[i]); mn = fminf(mn, vd[i]);
        }
        for (int o = 16; o; o >>= 1) {
            mD = fmaxf(mD, __shfl_xor_sync(0xffffffffu, mD, o));
            mO = fmaxf(mO, __shfl_xor_sync(0xffffffffu, mO, o));
            mn = fminf(mn, __shfl_xor_sync(0xffffffffu, mn, o));
        }
        float sD = 0.f, tO = 0.f, uD = 0.f, sO = 0.f;
#pragma unroll
        for (int i = 0; i < 8; i++) {
            float e = expf(vd[i] - mD);
            sD += e; tO += e * vo[i]; uD += e * vd[i];
            sO += expf(vo[i] - mO);
        }
        for (int o = 16; o; o >>= 1) {
            sD += __shfl_xor_sync(0xffffffffu, sD, o);
            tO += __shfl_xor_sync(0xffffffffu, tO, o);
            uD += __shfl_xor_sync(0xffffffffu, uD, o);
            sO += __shfl_xor_sync(0xffffffffu, sO, o);
        }
        amD[k] = mD; asD[k] = sD; atO[k] = tO; auD[k] = uD; amO[k] = mO; asO[k] = sO;
        if (lane == 0) atomicMin(&g_minbits[k], fkey(mn));
    }
    __syncthreads();   // sacc zero visible

    // --- fused hsoft: lanes 0..6 each handle one subset ---
    if (lane < 7) {
        const int masks[7] = {1, 2, 4, 5, 6, 3, 7}; // {1},{2},{3},{1,3},{2,3},{1,2},{1,2,3}
        int m = masks[lane];
        float M = -INFINITY, MO = -INFINITY;
#pragma unroll
        for (int k = 0; k < 3; k++)
            if (m & (1 << k)) { M = fmaxf(M, amD[k]); MO = fmaxf(MO, amO[k]); }
        float S = 0.f, T = 0.f, U = 0.f, SO = 0.f;
#pragma unroll
        for (int k = 0; k < 3; k++)
            if (m & (1 << k)) {
                float w = expf(amD[k] - M);
                S += asD[k] * w;
                T += atO[k] * w;
                U += auD[k] * w;
                SO += asO[k] * expf(amO[k] - MO);
            }
        float lseD = M + logf(S);
        float lseO = MO + logf(SO);
        float Spo = T / S, Spd = U / S;
        float ce = lseO - Spo;
        float kl = (Spd - lseD) - (Spo - lseO);
        atomicAdd(&sacc[lane], (double)ce);
        atomicAdd(&sacc[7 + lane], (double)kl);
    }
    __syncthreads();
    if (threadIdx.x < 14) atomicAdd(&g_ck[threadIdx.x], sacc[threadIdx.x]);
}

// packed-slot insert: word = key<<9 | count (count <= 256 fits 9 bits, keys <= 23 bits)
__device__ __forceinline__ uint32_t hinsert(uint32_t* table, uint32_t key) {
    uint32_t h = (key * 2654435769u) >> 23;
    uint32_t packed = (key << 9) | 1u;
    for (;;) {
        uint32_t old = atomicCAS(&table[h], 0u, packed);
        if (old == 0u) return h;
        if ((old >> 9) == key) { atomicAdd(&table[h], 1u); return h; }
        h = (h + 1) & (HS - 1);
    }
}

// ------- entropy: 7 concurrent per-row hash tables, raw-label pair keys -------
// table order: 0:{1} 1:{2} 2:{3} 3:{1,3} 4:{2,3} 5:{1,2} 6:{1,2,3}
__global__ void entropy_kernel(const float* __restrict__ d1, const float* __restrict__ d2,
                               const float* __restrict__ d3, float* __restrict__ out) {
    __shared__ uint32_t tab[7 * HS];
    __shared__ float red[8 * 7];
    int row = blockIdx.x, t = threadIdx.x;
    float lo1 = floorf(funkey(g_minbits[0]));
    float lo2 = floorf(funkey(g_minbits[1]));
    float lo3 = floorf(funkey(g_minbits[2]));
    int idx = row * ND + t;
    uint32_t l1 = (uint32_t)(int)floorf(__fdiv_rn(d1[idx] - lo1, 0.01f));
    uint32_t l2 = (uint32_t)(int)floorf(__fdiv_rn(d2[idx] - lo2, 0.01f));
    uint32_t l3 = (uint32_t)(int)floorf(__fdiv_rn(d3[idx] - lo3, 0.01f));

    // vectorized zero
    uint2* tz = (uint2*)tab;
#pragma unroll
    for (int i = 0; i < 7; i++) tz[t + i * ND] = make_uint2(0u, 0u);
    __syncthreads();

    // 6 independent inserts (singles use raw labels; pairs use raw-label packs <=20 bits)
    hinsert(tab + 0 * HS, l1);
    hinsert(tab + 1 * HS, l2);
    hinsert(tab + 2 * HS, l3);
    hinsert(tab + 3 * HS, l1 | (l3 << 10));
    hinsert(tab + 4 * HS, l2 | (l3 << 10));
    uint32_t s12 = hinsert(tab + 5 * HS, l1 | (l2 << 10));
    // triple: own pair-12 slot id (9b, consistent across threads) + l3 (10b) = 19 bits
    hinsert(tab + 6 * HS, s12 | (l3 << 9));
    __syncthreads();

    // table scan: A_s = sum over distinct v of c*log(c); word i*256+t -> subset i>>1
    float A[7] = {0.f, 0.f, 0.f, 0.f, 0.f, 0.f, 0.f};
#pragma unroll
    for (int i = 0; i < 14; i++) {
        uint32_t w = tab[i * ND + t];
        if (w) {
            float c = (float)(w & 0x1FFu);
            A[i >> 1] += c * logf(c);
        }
    }

    int lane = t & 31, w = t >> 5;
#pragma unroll
    for (int k = 0; k < 7; k++) {
        float x = A[k];
        for (int o = 16; o; o >>= 1) x += __shfl_xor_sync(0xffffffffu, x, o);
        if (lane == 0) red[w * 7 + k] = x;
    }
    __syncthreads();
    if (t < 7) {
        double a = 0.0;
        for (int w2 = 0; w2 < 8; w2++) a += (double)red[w2 * 7 + t];
        // row entropy H = log(256) - A/256
        atomicAdd(&g_acc[1 + t], 5.545177444479562 - a * (1.0 / 256.0));
    }

    // ------- last block: assemble final scalar -------
    __syncthreads();
    if (t == 0) {
        __threadfence();
        unsigned int old = atomicInc(&g_done, gridDim.x - 1);
        if (old == gridDim.x - 1) {
            const int masks[7] = {1, 2, 4, 5, 6, 3, 7};
            double Hout[7];
            for (int s = 0; s < 7; s++) {
                int C = ND * __popc(masks[s]);
                Hout[s] = g_ck[s] / (double)NB - g_ck[7 + s] / ((double)NB * (double)C);
            }
            double Hd1 = g_acc[1] / NB, Hd2 = g_acc[2] / NB, Hd3 = g_acc[3] / NB;
            double Hin13 = g_acc[4] / NB, Hin23 = g_acc[5] / NB, Hin12 = g_acc[6] / NB;
            double H1 = Hd1 - Hout[0];
            double H2 = Hd2 - Hout[1];
            double H3 = Hd3 - Hout[2];
            double data13 = Hd1 + Hd3 - Hin13;
            double data23 = Hd2 + Hd3 - Hin23;
            double data12 = Hd1 + Hd2 - Hin12;
            double lab13 = Hout[0] + Hout[2] - Hout[3];
            double lab23 = Hout[1] + Hout[2] - Hout[4];
            double lab12 = Hout[0] + Hout[1] - Hout[5];
            double MI13 = lab13 - data13, MI23 = lab23 - data23, MI12 = lab12 - data12;
            double aveDataCMI = g_acc[4] + g_acc[5] - g_acc[3] - g_acc[7];
            double aveLabCMI = Hout[4] - Hout[2] + Hout[3] - Hout[6];
            double CMI = aveLabCMI - aveDataCMI;
            double mse = 0.5 * (g_acc[0] / ((double)NB * (double)NDT));
            double loss = 0.5 * mse
                        + 0.25 * (H1 * H1 + H2 * H2 + H3 * H3)
                        + 0.25 * (MI13 * MI13 + MI23 * MI23 + MI12 * MI12 + CMI * CMI);
            out[0] = (float)loss;
        }
    }
}

extern "C" void kernel_launch(void* const* d_in, const int* in_sizes, int n_in,
                              void* d_out, int out_size) {
    (void)in_sizes; (void)n_in; (void)out_size;
    const float* data  = (const float*)d_in[0];
    const float* data1 = (const float*)d_in[1];
    const float* data2 = (const float*)d_in[2];
    const float* data3 = (const float*)d_in[3];
    const float* out1  = (const float*)d_in[4];
    const float* out2  = (const float*)d_in[5];
    const float* out3  = (const float*)d_in[6];
    const float* outp  = (const float*)d_in[7];

    init_kernel<<<1, 32>>>();
    stats_kernel<<<NB / 8, 256>>>(data1, data2, data3, out1, out2, out3, data, outp);
    entropy_kernel<<<NB, 256>>>(data1, data2, data3, (float*)d_out);
}

// round 5
// speedup vs baseline: 1.9717x; 1.9717x over previous
#include <cuda_runtime.h>
#include <stdint.h>
#include <math.h>

#define NB 2048
#define ND 256
#define NDT 768
#define HS 512
#define SBLK 256                 // stats blocks (8 rows each)
#define TOTBLK (NB + SBLK)

// zero/static-initialized at module load; finish block resets them each run
__device__ double g_acc[8];      // [0]=mse sumsq, [1..7]=S1,S2,S3,S13,S23,S12,S123
__device__ double g_ck[14];      // ce,kl sums per 7 masks
__device__ unsigned int g_minbits[3] = {0xFFFFFFFFu, 0xFFFFFFFFu, 0xFFFFFFFFu};
__device__ unsigned int g_done;  // auto-wraps via atomicInc

__device__ __forceinline__ unsigned int fkey(float f) {
    unsigned int u = __float_as_uint(f);
    return (u & 0x80000000u) ? ~u : (u | 0x80000000u);
}
__device__ __forceinline__ float funkey(unsigned int u) {
    return __uint_as_float((u & 0x80000000u) ? (u & 0x7FFFFFFFu) : ~u);
}

// FMA-pipe exp (no MUFU): deg-5 Taylor of 2^f, x in [-90, 0]
__device__ __forceinline__ float fexp(float x) {
    float t = x * 1.44269504f;
    float fi = floorf(t);
    float f = t - fi;
    float p = 0.00134086f;
    p = fmaf(p, f, 0.00961812f);
    p = fmaf(p, f, 0.05550411f);
    p = fmaf(p, f, 0.24022651f);
    p = fmaf(p, f, 0.69314718f);
    p = fmaf(p, f, 1.0f);
    return __int_as_float(((int)fi + 127) << 23) * p;
}

// ---------------- kernel 1: global mins of d1/d2/d3 + MSE ----------------
__global__ void minmse_kernel(const float* __restrict__ d1, const float* __restrict__ d2,
                              const float* __restrict__ d3,
                              const float* __restrict__ data, const float* __restrict__ outp) {
    __shared__ float smn[3][8];
    __shared__ float ssum[8];
    int tid = blockIdx.x * blockDim.x + threadIdx.x;   // grid 512*256 = 131072
    int lane = threadIdx.x & 31, w = threadIdx.x >> 5;

    const float4* a1 = (const float4*)d1;
    const float4* a2 = (const float4*)d2;
    const float4* a3 = (const float4*)d3;
    float mn[3];
    {
        float4 v1 = a1[tid], v2 = a2[tid], v3 = a3[tid];  // 131072 f4 exactly
        mn[0] = fminf(fminf(v1.x, v1.y), fminf(v1.z, v1.w));
        mn[1] = fminf(fminf(v2.x, v2.y), fminf(v2.z, v2.w));
        mn[2] = fminf(fminf(v3.x, v3.y), fminf(v3.z, v3.w));
    }
    float s = 0.f;
    const float4* da = (const float4*)data;
    const float4* db = (const float4*)outp;
#pragma unroll
    for (int i = 0; i < 3; i++) {                      // 393216 f4 total
        int idx = tid + i * 131072;
        float4 x = da[idx], y = db[idx];
        float e0 = x.x - y.x, e1 = x.y - y.y, e2 = x.z - y.z, e3 = x.w - y.w;
        s += e0 * e0 + e1 * e1 + e2 * e2 + e3 * e3;
    }
    for (int o = 16; o; o >>= 1) {
        s += __shfl_xor_sync(0xffffffffu, s, o);
#pragma unroll
        for (int k = 0; k < 3; k++) mn[k] = fminf(mn[k], __shfl_xor_sync(0xffffffffu, mn[k], o));
    }
    if (lane == 0) {
        smn[0][w] = mn[0]; smn[1][w] = mn[1]; smn[2][w] = mn[2]; ssum[w] = s;
    }
    __syncthreads();
    if (threadIdx.x == 0) {
        float m0 = smn[0][0], m1 = smn[1][0], m2 = smn[2][0];
        double tot = (double)ssum[0];
        for (int i = 1; i < 8; i++) {
            m0 = fminf(m0, smn[0][i]); m1 = fminf(m1, smn[1][i]); m2 = fminf(m2, smn[2][i]);
            tot += (double)ssum[i];
        }
        atomicMin(&g_minbits[0], fkey(m0));
        atomicMin(&g_minbits[1], fkey(m1));
        atomicMin(&g_minbits[2], fkey(m2));
        atomicAdd(&g_acc[0], tot);
    }
}

// packed-slot insert: word = key<<9 | count (count <= 256 fits 9 bits, keys <= 23 bits)
__device__ __forceinline__ uint32_t hinsert(uint32_t* table, uint32_t key) {
    uint32_t h = (key * 2654435769u) >> 23;
    uint32_t packed = (key << 9) | 1u;
    for (;;) {
        uint32_t old = atomicCAS(&table[h], 0u, packed);
        if (old == 0u) return h;
        if ((old >> 9) == key) { atomicAdd(&table[h], 1u); return h; }
        h = (h + 1) & (HS - 1);
    }
}

// ---------------- mega kernel: stats blocks (0..255) + entropy blocks (256..2303) ----------------
__global__ void __launch_bounds__(256) mega_kernel(
        const float* __restrict__ d1, const float* __restrict__ d2,
        const float* __restrict__ d3,
        const float* __restrict__ o1, const float* __restrict__ o2,
        const float* __restrict__ o3, float* __restrict__ out) {
    __shared__ uint32_t tab[7 * HS];     // 14 KB (entropy path)
    __shared__ float red[8 * 7];
    __shared__ double sacc[14];          // stats path
    int bid = blockIdx.x, t = threadIdx.x;
    int lane = t & 31, w = t >> 5;

    if (bid < SBLK) {
        // ======== stats path: 8 rows, one warp per row ========
        if (t < 14) sacc[t] = 0.0;
        int gw = bid * 8 + w;
        const float* ds[3] = {d1, d2, d3};
        const float* os[3] = {o1, o2, o3};
        float amD[3], asD[3], atO[3], auD[3], amO[3], asO[3];
#pragma unroll
        for (int k = 0; k < 3; k++) {
            const float* dp = ds[k] + gw * ND;
            const float* op = os[k] + gw * ND;
            float vd[8], vo[8];
#pragma unroll
            for (int i = 0; i < 8; i++) { vd[i] = dp[lane + 32 * i]; vo[i] = op[lane + 32 * i]; }
            float mD = -INFINITY, mO = -INFINITY;
#pragma unroll
            for (int i = 0; i < 8; i++) { mD = fmaxf(mD, vd[i]); mO = fmaxf(mO, vo[i]); }
            for (int o = 16; o; o >>= 1) {
                mD = fmaxf(mD, __shfl_xor_sync(0xffffffffu, mD, o));
                mO = fmaxf(mO, __shfl_xor_sync(0xffffffffu, mO, o));
            }
            float sD = 0.f, tO = 0.f, uD = 0.f, sO = 0.f;
#pragma unroll
            for (int i = 0; i < 8; i++) {
                float e = __expf(vd[i] - mD);       // MUFU path
                sD += e; tO += e * vo[i]; uD += e * vd[i];
                sO += fexp(vo[i] - mO);             // FMA path
            }
            for (int o = 16; o; o >>= 1) {
                sD += __shfl_xor_sync(0xffffffffu, sD, o);
                tO += __shfl_xor_sync(0xffffffffu, tO, o);
                uD += __shfl_xor_sync(0xffffffffu, uD, o);
                sO += __shfl_xor_sync(0xffffffffu, sO, o);
            }
            amD[k] = mD; asD[k] = sD; atO[k] = tO; auD[k] = uD; amO[k] = mO; asO[k] = sO;
        }
        __syncthreads();   // sacc zero visible
        if (lane < 7) {
            const int masks[7] = {1, 2, 4, 5, 6, 3, 7};
            int m = masks[lane];
            float M = -INFINITY, MO = -INFINITY;
#pragma unroll
            for (int k = 0; k < 3; k++)
                if (m & (1 << k)) { M = fmaxf(M, amD[k]); MO = fmaxf(MO, amO[k]); }
            float S = 0.f, T = 0.f, U = 0.f, SO = 0.f;
#pragma unroll
            for (int k = 0; k < 3; k++)
                if (m & (1 << k)) {
                    float wt = __expf(amD[k] - M);
                    S += asD[k] * wt;
                    T += atO[k] * wt;
                    U += auD[k] * wt;
                    SO += asO[k] * __expf(amO[k] - MO);
                }
            float lseD = M + logf(S);
            float lseO = MO + logf(SO);
            float Spo = T / S, Spd = U / S;
            atomicAdd(&sacc[lane], (double)(lseO - Spo));                    // ce
            atomicAdd(&sacc[7 + lane], (double)((Spd - lseD) - (Spo - lseO))); // kl
        }
        __syncthreads();
        if (t < 14) atomicAdd(&g_ck[t], sacc[t]);
    } else {
        // ======== entropy path: one row, candidate-pruned hash counting ========
        int row = bid - SBLK;
        float lo1 = floorf(funkey(g_minbits[0]));
        float lo2 = floorf(funkey(g_minbits[1]));
        float lo3 = floorf(funkey(g_minbits[2]));
        int idx = row * ND + t;
        uint32_t l1 = (uint32_t)(int)floorf(__fdiv_rn(d1[idx] - lo1, 0.01f));
        uint32_t l2 = (uint32_t)(int)floorf(__fdiv_rn(d2[idx] - lo2, 0.01f));
        uint32_t l3 = (uint32_t)(int)floorf(__fdiv_rn(d3[idx] - lo3, 0.01f));

        // zero 3584 words with uint4
        uint4* tz = (uint4*)tab;
        tz[t] = make_uint4(0, 0, 0, 0);
        tz[t + 256] = make_uint4(0, 0, 0, 0);
        tz[t + 512] = make_uint4(0, 0, 0, 0);
        if (t < 128) tz[t + 768] = make_uint4(0, 0, 0, 0);
        __syncthreads();

        // singles
        uint32_t h1 = hinsert(tab + 0 * HS, l1);
        uint32_t h2 = hinsert(tab + 1 * HS, l2);
        uint32_t h3 = hinsert(tab + 2 * HS, l3);
        __syncthreads();
        uint32_t c1 = tab[0 * HS + h1] & 511u;
        uint32_t c2 = tab[1 * HS + h2] & 511u;
        uint32_t c3 = tab[2 * HS + h3] & 511u;

        // pairs: only elements whose BOTH single counts exceed 1 can have pair count > 1
        bool a13 = (c1 > 1u) & (c3 > 1u);
        bool a23 = (c2 > 1u) & (c3 > 1u);
        bool a12 = (c1 > 1u) & (c2 > 1u);
        uint32_t h13 = 0, h23 = 0, h12 = 0;
        if (a13) h13 = hinsert(tab + 3 * HS, l1 | (l3 << 10));
        if (a23) h23 = hinsert(tab + 4 * HS, l2 | (l3 << 10));
        if (a12) h12 = hinsert(tab + 5 * HS, l1 | (l2 << 10));
        __syncthreads();
        uint32_t c13 = a13 ? (tab[3 * HS + h13] & 511u) : 1u;
        uint32_t c23 = a23 ? (tab[4 * HS + h23] & 511u) : 1u;
        uint32_t c12 = a12 ? (tab[5 * HS + h12] & 511u) : 1u;

        // triple: candidates need c12>1 and c3>1; key = pair12 slot id (9b) | l3<<9
        bool a123 = (c12 > 1u) & (c3 > 1u);
        uint32_t h123 = 0;
        if (a123) h123 = hinsert(tab + 6 * HS, h12 | (l3 << 9));
        __syncthreads();
        uint32_t c123 = a123 ? (tab[6 * HS + h123] & 511u) : 1u;

        // per-element log counts (log 1 = 0 skipped)
        float A[7];
        A[0] = (c1 > 1u) ? logf((float)c1) : 0.f;
        A[1] = (c2 > 1u) ? logf((float)c2) : 0.f;
        A[2] = (c3 > 1u) ? logf((float)c3) : 0.f;
        A[3] = (c13 > 1u) ? logf((float)c13) : 0.f;
        A[4] = (c23 > 1u) ? logf((float)c23) : 0.f;
        A[5] = (c12 > 1u) ? logf((float)c12) : 0.f;
        A[6] = (c123 > 1u) ? logf((float)c123) : 0.f;

#pragma unroll
        for (int k = 0; k < 7; k++) {
            float x = A[k];
            for (int o = 16; o; o >>= 1) x += __shfl_xor_sync(0xffffffffu, x, o);
            if (lane == 0) red[w * 7 + k] = x;
        }
        __syncthreads();
        if (t < 7) {
            double a = 0.0;
            for (int w2 = 0; w2 < 8; w2++) a += (double)red[w2 * 7 + t];
            // row entropy H = log(256) - A/256
            atomicAdd(&g_acc[1 + t], 5.545177444479562 - a * (1.0 / 256.0));
        }
    }

    // ======== last block: assemble scalar + reset state for next replay ========
    __syncthreads();
    if (t == 0) {
        __threadfence();
        unsigned int old = atomicInc(&g_done, TOTBLK - 1);   // wraps to 0 on last
        if (old == TOTBLK - 1) {
            const int masks[7] = {1, 2, 4, 5, 6, 3, 7};
            double Hout[7];
            for (int s = 0; s < 7; s++) {
                int C = ND * __popc(masks[s]);
                Hout[s] = g_ck[s] / (double)NB - g_ck[7 + s] / ((double)NB * (double)C);
            }
            double Hd1 = g_acc[1] / NB, Hd2 = g_acc[2] / NB, Hd3 = g_acc[3] / NB;
            double Hin13 = g_acc[4] / NB, Hin23 = g_acc[5] / NB, Hin12 = g_acc[6] / NB;
            double H1 = Hd1 - Hout[0];
            double H2 = Hd2 - Hout[1];
            double H3 = Hd3 - Hout[2];
            double data13 = Hd1 + Hd3 - Hin13;
            double data23 = Hd2 + Hd3 - Hin23;
            double data12 = Hd1 + Hd2 - Hin12;
            double lab13 = Hout[0] + Hout[2] - Hout[3];
            double lab23 = Hout[1] + Hout[2] - Hout[4];
            double lab12 = Hout[0] + Hout[1] - Hout[5];
            double MI13 = lab13 - data13, MI23 = lab23 - data23, MI12 = lab12 - data12;
            double aveDataCMI = g_acc[4] + g_acc[5] - g_acc[3] - g_acc[7];
            double aveLabCMI = Hout[4] - Hout[2] + Hout[3] - Hout[6];
            double CMI = aveLabCMI - aveDataCMI;
            double mse = 0.5 * (g_acc[0] / ((double)NB * (double)NDT));
            double loss = 0.5 * mse
                        + 0.25 * (H1 * H1 + H2 * H2 + H3 * H3)
                        + 0.25 * (MI13 * MI13 + MI23 * MI23 + MI12 * MI12 + CMI * CMI);
            out[0] = (float)loss;
            // reset for next graph replay
            for (int i = 0; i < 8; i++) g_acc[i] = 0.0;
            for (int i = 0; i < 14; i++) g_ck[i] = 0.0;
            g_minbits[0] = 0xFFFFFFFFu; g_minbits[1] = 0xFFFFFFFFu; g_minbits[2] = 0xFFFFFFFFu;
        }
    }
}

extern "C" void kernel_launch(void* const* d_in, const int* in_sizes, int n_in,
                              void* d_out, int out_size) {
    (void)in_sizes; (void)n_in; (void)out_size;
    const float* data  = (const float*)d_in[0];
    const float* data1 = (const float*)d_in[1];
    const float* data2 = (const float*)d_in[2];
    const float* data3 = (const float*)d_in[3];
    const float* out1  = (const float*)d_in[4];
    const float* out2  = (const float*)d_in[5];
    const float* out3  = (const float*)d_in[6];
    const float* outp  = (const float*)d_in[7];

    minmse_kernel<<<512, 256>>>(data1, data2, data3, data, outp);
    mega_kernel<<<TOTBLK, 256>>>(data1, data2, data3, out1, out2, out3, (float*)d_out);
}

// round 6
// speedup vs baseline: 2.0554x; 1.0425x over previous
#include <cuda_runtime.h>
#include <stdint.h>
#include <math.h>

#define NB 2048
#define ND 256
#define NDT 768
#define HS 512
#define NBINW 1024               // u32 words per variable = 2048 u16 bins
#define SBLK 256                 // stats blocks (8 rows each)
#define TOTBLK (NB + SBLK)

// zero/static-initialized at module load; finish block resets them each run
__device__ double g_acc[8];      // [0]=mse sumsq, [1..7]=S1,S2,S3,S13,S23,S12,S123
__device__ double g_ck[14];      // ce,kl sums per 7 masks
__device__ unsigned int g_minbits[3] = {0xFFFFFFFFu, 0xFFFFFFFFu, 0xFFFFFFFFu};
__device__ unsigned int g_done;  // auto-wraps via atomicInc

__device__ __forceinline__ unsigned int fkey(float f) {
    unsigned int u = __float_as_uint(f);
    return (u & 0x80000000u) ? ~u : (u | 0x80000000u);
}
__device__ __forceinline__ float funkey(unsigned int u) {
    return __uint_as_float((u & 0x80000000u) ? (u & 0x7FFFFFFFu) : ~u);
}

// FMA-pipe exp (no MUFU): 2^f split, f in [0,1)
__device__ __forceinline__ float fexp(float x) {
    float t = x * 1.44269504f;
    float fi = floorf(t);
    float f = t - fi;
    float p = 0.00134086f;
    p = fmaf(p, f, 0.00961812f);
    p = fmaf(p, f, 0.05550411f);
    p = fmaf(p, f, 0.24022651f);
    p = fmaf(p, f, 0.69314718f);
    p = fmaf(p, f, 1.0f);
    return __int_as_float(((int)fi + 127) << 23) * p;
}

// ---------------- kernel 1: global mins of d1/d2/d3 only ----------------
__global__ void min_kernel(const float* __restrict__ d1, const float* __restrict__ d2,
                           const float* __restrict__ d3) {
    __shared__ float smn[3][8];
    int tid = blockIdx.x * blockDim.x + threadIdx.x;   // grid 512*256 = 131072
    int lane = threadIdx.x & 31, w = threadIdx.x >> 5;
    const float4* a1 = (const float4*)d1;
    const float4* a2 = (const float4*)d2;
    const float4* a3 = (const float4*)d3;
    float4 v1 = a1[tid], v2 = a2[tid], v3 = a3[tid];   // 131072 f4 exactly
    float mn[3];
    mn[0] = fminf(fminf(v1.x, v1.y), fminf(v1.z, v1.w));
    mn[1] = fminf(fminf(v2.x, v2.y), fminf(v2.z, v2.w));
    mn[2] = fminf(fminf(v3.x, v3.y), fminf(v3.z, v3.w));
    for (int o = 16; o; o >>= 1)
#pragma unroll
        for (int k = 0; k < 3; k++) mn[k] = fminf(mn[k], __shfl_xor_sync(0xffffffffu, mn[k], o));
    if (lane == 0) { smn[0][w] = mn[0]; smn[1][w] = mn[1]; smn[2][w] = mn[2]; }
    __syncthreads();
    if (threadIdx.x == 0) {
        float m0 = smn[0][0], m1 = smn[1][0], m2 = smn[2][0];
        for (int i = 1; i < 8; i++) {
            m0 = fminf(m0, smn[0][i]); m1 = fminf(m1, smn[1][i]); m2 = fminf(m2, smn[2][i]);
        }
        atomicMin(&g_minbits[0], fkey(m0));
        atomicMin(&g_minbits[1], fkey(m1));
        atomicMin(&g_minbits[2], fkey(m2));
    }
}

// packed-slot insert: word = key<<9 | count (count <= 256 fits 9 bits, keys <= 23 bits)
__device__ __forceinline__ uint32_t hinsert(uint32_t* table, uint32_t key) {
    uint32_t h = (key * 2654435769u) >> 23;
    uint32_t packed = (key << 9) | 1u;
    for (;;) {
        uint32_t old = atomicCAS(&table[h], 0u, packed);
        if (old == 0u) return h;
        if ((old >> 9) == key) { atomicAdd(&table[h], 1u); return h; }
        h = (h + 1) & (HS - 1);
    }
}

// ---------------- mega kernel: stats+MSE blocks (0..255) + entropy blocks (256..2303) ----------------
__global__ void __launch_bounds__(256) mega_kernel(
        const float* __restrict__ d1, const float* __restrict__ d2,
        const float* __restrict__ d3,
        const float* __restrict__ o1, const float* __restrict__ o2,
        const float* __restrict__ o3,
        const float* __restrict__ data, const float* __restrict__ outp,
        float* __restrict__ out) {
    __shared__ uint32_t cnt[3 * NBINW];  // 12 KB direct-mapped packed u16 single counts
    __shared__ uint32_t tab[4 * HS];     // 8 KB: pair13, pair23, pair12, triple
    __shared__ float red[8 * 7];
    __shared__ double sacc[14];
    int bid = blockIdx.x, t = threadIdx.x;
    int lane = t & 31, w = t >> 5;

    if (bid < SBLK) {
        // ======== stats path: fused MSE slice + 8 rows softmax stats ========
        if (t < 14) sacc[t] = 0.0;
        // MSE slice: 393216 f4 total over 256 blocks = 6 f4/thread
        {
            const float4* da = (const float4*)data;
            const float4* db = (const float4*)outp;
            float s = 0.f;
#pragma unroll
            for (int i = 0; i < 6; i++) {
                int idx = bid * 256 + t + i * 65536;
                float4 x = da[idx], y = db[idx];
                float e0 = x.x - y.x, e1 = x.y - y.y, e2 = x.z - y.z, e3 = x.w - y.w;
                s += e0 * e0 + e1 * e1 + e2 * e2 + e3 * e3;
            }
            for (int o = 16; o; o >>= 1) s += __shfl_xor_sync(0xffffffffu, s, o);
            if (lane == 0) atomicAdd(&g_acc[0], (double)s);
        }
        int gw = bid * 8 + w;
        const float* ds[3] = {d1, d2, d3};
        const float* os[3] = {o1, o2, o3};
        float amD[3], asD[3], atO[3], auD[3], amO[3], asO[3];
#pragma unroll
        for (int k = 0; k < 3; k++) {
            const float* dp = ds[k] + gw * ND;
            const float* op = os[k] + gw * ND;
            float vd[8], vo[8];
#pragma unroll
            for (int i = 0; i < 8; i++) { vd[i] = dp[lane + 32 * i]; vo[i] = op[lane + 32 * i]; }
            float mD = -INFINITY, mO = -INFINITY;
#pragma unroll
            for (int i = 0; i < 8; i++) { mD = fmaxf(mD, vd[i]); mO = fmaxf(mO, vo[i]); }
            for (int o = 16; o; o >>= 1) {
                mD = fmaxf(mD, __shfl_xor_sync(0xffffffffu, mD, o));
                mO = fmaxf(mO, __shfl_xor_sync(0xffffffffu, mO, o));
            }
            float sD = 0.f, tO = 0.f, uD = 0.f, sO = 0.f;
#pragma unroll
            for (int i = 0; i < 8; i++) {
                float e = __expf(vd[i] - mD);       // MUFU path
                sD += e; tO += e * vo[i]; uD += e * vd[i];
                sO += fexp(vo[i] - mO);             // FMA path
            }
            for (int o = 16; o; o >>= 1) {
                sD += __shfl_xor_sync(0xffffffffu, sD, o);
                tO += __shfl_xor_sync(0xffffffffu, tO, o);
                uD += __shfl_xor_sync(0xffffffffu, uD, o);
                sO += __shfl_xor_sync(0xffffffffu, sO, o);
            }
            amD[k] = mD; asD[k] = sD; atO[k] = tO; auD[k] = uD; amO[k] = mO; asO[k] = sO;
        }
        __syncthreads();   // sacc zero visible
        if (lane < 7) {
            const int masks[7] = {1, 2, 4, 5, 6, 3, 7};
            int m = masks[lane];
            float M = -INFINITY, MO = -INFINITY;
#pragma unroll
            for (int k = 0; k < 3; k++)
                if (m & (1 << k)) { M = fmaxf(M, amD[k]); MO = fmaxf(MO, amO[k]); }
            float S = 0.f, T = 0.f, U = 0.f, SO = 0.f;
#pragma unroll
            for (int k = 0; k < 3; k++)
                if (m & (1 << k)) {
                    float wt = __expf(amD[k] - M);
                    S += asD[k] * wt;
                    T += atO[k] * wt;
                    U += auD[k] * wt;
                    SO += asO[k] * __expf(amO[k] - MO);
                }
            float lseD = M + logf(S);
            float lseO = MO + logf(SO);
            float Spo = T / S, Spd = U / S;
            atomicAdd(&sacc[lane], (double)(lseO - Spo));                      // ce
            atomicAdd(&sacc[7 + lane], (double)((Spd - lseD) - (Spo - lseO))); // kl
        }
        __syncthreads();
        if (t < 14) atomicAdd(&g_ck[t], sacc[t]);
    } else {
        // ======== entropy path: one row, direct singles + candidate-pruned pairs ========
        int row = bid - SBLK;
        float lo1 = floorf(funkey(g_minbits[0]));
        float lo2 = floorf(funkey(g_minbits[1]));
        float lo3 = floorf(funkey(g_minbits[2]));
        int idx = row * ND + t;
        uint32_t l1 = (uint32_t)(int)floorf(__fdiv_rn(d1[idx] - lo1, 0.01f));
        uint32_t l2 = (uint32_t)(int)floorf(__fdiv_rn(d2[idx] - lo2, 0.01f));
        uint32_t l3 = (uint32_t)(int)floorf(__fdiv_rn(d3[idx] - lo3, 0.01f));

        // zero 3*1024 + 4*512 = 5120 words with uint4 (1280 uint4, 5/thread)
        {
            uint4* cz = (uint4*)cnt;
#pragma unroll
            for (int i = 0; i < 3; i++) cz[t + i * 256] = make_uint4(0, 0, 0, 0);
            uint4* tz = (uint4*)tab;
            tz[t] = make_uint4(0, 0, 0, 0);
            if (t < 256) tz[t + 256] = make_uint4(0, 0, 0, 0);
        }
        __syncthreads();

        // singles: one plain atomicAdd each into packed u16 bins
        atomicAdd(&cnt[0 * NBINW + (l1 >> 1)], (l1 & 1u) ? 0x10000u : 1u);
        atomicAdd(&cnt[1 * NBINW + (l2 >> 1)], (l2 & 1u) ? 0x10000u : 1u);
        atomicAdd(&cnt[2 * NBINW + (l3 >> 1)], (l3 & 1u) ? 0x10000u : 1u);
        __syncthreads();
        uint32_t c1 = (cnt[0 * NBINW + (l1 >> 1)] >> ((l1 & 1u) * 16)) & 0xFFFFu;
        uint32_t c2 = (cnt[1 * NBINW + (l2 >> 1)] >> ((l2 & 1u) * 16)) & 0xFFFFu;
        uint32_t c3 = (cnt[2 * NBINW + (l3 >> 1)] >> ((l3 & 1u) * 16)) & 0xFFFFu;

        // pairs: only elements with BOTH single counts > 1 can have pair count > 1
        bool a13 = (c1 > 1u) & (c3 > 1u);
        bool a23 = (c2 > 1u) & (c3 > 1u);
        bool a12 = (c1 > 1u) & (c2 > 1u);
        uint32_t h13 = 0, h23 = 0, h12 = 0;
        if (a13) h13 = hinsert(tab + 0 * HS, l1 | (l3 << 11));
        if (a23) h23 = hinsert(tab + 1 * HS, l2 | (l3 << 11));
        if (a12) h12 = hinsert(tab + 2 * HS, l1 | (l2 << 11));
        __syncthreads();
        uint32_t c13 = a13 ? (tab[0 * HS + h13] & 511u) : 1u;
        uint32_t c23 = a23 ? (tab[1 * HS + h23] & 511u) : 1u;
        uint32_t c12 = a12 ? (tab[2 * HS + h12] & 511u) : 1u;

        // triple: candidates need c12>1 and c3>1; key = pair12 slot id (9b) | l3<<9
        bool a123 = (c12 > 1u) & (c3 > 1u);
        uint32_t h123 = 0;
        if (a123) h123 = hinsert(tab + 3 * HS, h12 | (l3 << 9));
        __syncthreads();
        uint32_t c123 = a123 ? (tab[3 * HS + h123] & 511u) : 1u;

        // per-element log counts (log 1 = 0)
        float A[7];
        A[0] = (c1 > 1u) ? logf((float)c1) : 0.f;
        A[1] = (c2 > 1u) ? logf((float)c2) : 0.f;
        A[2] = (c3 > 1u) ? logf((float)c3) : 0.f;
        A[3] = (c13 > 1u) ? logf((float)c13) : 0.f;
        A[4] = (c23 > 1u) ? logf((float)c23) : 0.f;
        A[5] = (c12 > 1u) ? logf((float)c12) : 0.f;
        A[6] = (c123 > 1u) ? logf((float)c123) : 0.f;

#pragma unroll
        for (int k = 0; k < 7; k++) {
            float x = A[k];
            for (int o = 16; o; o >>= 1) x += __shfl_xor_sync(0xffffffffu, x, o);
            if (lane == 0) red[w * 7 + k] = x;
        }
        __syncthreads();
        if (t < 7) {
            double a = 0.0;
            for (int w2 = 0; w2 < 8; w2++) a += (double)red[w2 * 7 + t];
            // row entropy H = log(256) - A/256
            atomicAdd(&g_acc[1 + t], 5.545177444479562 - a * (1.0 / 256.0));
        }
    }

    // ======== last block: assemble scalar + reset state for next replay ========
    __syncthreads();
    if (t == 0) {
        __threadfence();
        unsigned int old = atomicInc(&g_done, TOTBLK - 1);   // wraps to 0 on last
        if (old == TOTBLK - 1) {
            const int masks[7] = {1, 2, 4, 5, 6, 3, 7};
            double Hout[7];
            for (int s = 0; s < 7; s++) {
                int C = ND * __popc(masks[s]);
                Hout[s] = g_ck[s] / (double)NB - g_ck[7 + s] / ((double)NB * (double)C);
            }
            double Hd1 = g_acc[1] / NB, Hd2 = g_acc[2] / NB, Hd3 = g_acc[3] / NB;
            double Hin13 = g_acc[4] / NB, Hin23 = g_acc[5] / NB, Hin12 = g_acc[6] / NB;
            double H1 = Hd1 - Hout[0];
            double H2 = Hd2 - Hout[1];
            double H3 = Hd3 - Hout[2];
            double data13 = Hd1 + Hd3 - Hin13;
            double data23 = Hd2 + Hd3 - Hin23;
            double data12 = Hd1 + Hd2 - Hin12;
            double lab13 = Hout[0] + Hout[2] - Hout[3];
            double lab23 = Hout[1] + Hout[2] - Hout[4];
            double lab12 = Hout[0] + Hout[1] - Hout[5];
            double MI13 = lab13 - data13, MI23 = lab23 - data23, MI12 = lab12 - data12;
            double aveDataCMI = g_acc[4] + g_acc[5] - g_acc[3] - g_acc[7];
            double aveLabCMI = Hout[4] - Hout[2] + Hout[3] - Hout[6];
            double CMI = aveLabCMI - aveDataCMI;
            double mse = 0.5 * (g_acc[0] / ((double)NB * (double)NDT));
            double loss = 0.5 * mse
                        + 0.25 * (H1 * H1 + H2 * H2 + H3 * H3)
                        + 0.25 * (MI13 * MI13 + MI23 * MI23 + MI12 * MI12 + CMI * CMI);
            out[0] = (float)loss;
            // reset for next graph replay
            for (int i = 0; i < 8; i++) g_acc[i] = 0.0;
            for (int i = 0; i < 14; i++) g_ck[i] = 0.0;
            g_minbits[0] = 0xFFFFFFFFu; g_minbits[1] = 0xFFFFFFFFu; g_minbits[2] = 0xFFFFFFFFu;
        }
    }
}

extern "C" void kernel_launch(void* const* d_in, const int* in_sizes, int n_in,
                              void* d_out, int out_size) {
    (void)in_sizes; (void)n_in; (void)out_size;
    const float* data  = (const float*)d_in[0];
    const float* data1 = (const float*)d_in[1];
    const float* data2 = (const float*)d_in[2];
    const float* data3 = (const float*)d_in[3];
    const float* out1  = (const float*)d_in[4];
    const float* out2  = (const float*)d_in[5];
    const float* out3  = (const float*)d_in[6];
    const float* outp  = (const float*)d_in[7];

    min_kernel<<<512, 256>>>(data1, data2, data3);
    mega_kernel<<<TOTBLK, 256>>>(data1, data2, data3, out1, out2, out3, data, outp, (float*)d_out);
}